// round 10
// baseline (speedup 1.0000x reference)
#include <cuda_runtime.h>

#define CAM_FL  540.0f
#define HALF_W  320.0f
#define HALF_H  240.0f
#define CAM_W   640
#define CAM_H   480
#define HW      (CAM_H * CAM_W)
#define PB      1024     // particles per block (4 per thread)
#define TPB     256      // threads per block
#define CAP     256      // smem survivor capacity (mean ~46/block; overflow -> slow path)

__global__ __launch_bounds__(TPB, 6) void proj_kernel(
    const float* __restrict__ locs,
    const float* __restrict__ pose,
    const float* __restrict__ rotq,
    const float* __restrict__ depth,
    float* __restrict__ out,
    int N)
{
    // s_cam: 3 columns of (R row-major cols, -t) with t = pose·R
    __shared__ float s_cam[12];
    // record (16 floats): [0..7]=wx8 (aligned 8-slot x weights, pre-masked)
    // [8]=z  [9]=packed(bx | (ib+4)<<10)  [10..14]=wy[0..4]  [15]=pad
    __shared__ float s_rec[CAP][16];
    __shared__ float s_px[CAP];
    __shared__ float s_py[CAP];
    __shared__ float s_pz[CAP];
    __shared__ int   s_cnt;

    const int tid = threadIdx.x;
    const int b   = blockIdx.y;

    if (tid == 0) s_cnt = 0;

    const int  gpart = blockIdx.x * PB;
    const float* lpB = locs + ((long long)b * N + gpart) * 3;
    const int  i0 = 4 * tid;

    // ---- issue particle loads FIRST (overlap with warp-0 camera compute) ----
    float X[4], Y[4], Z[4];
    bool hv[4];
    if (gpart + PB <= N) {           // full block: 3x aligned LDG.128
        const float4* p = (const float4*)(lpB + i0 * 3);
        const float4 A  = p[0];
        const float4 Bv = p[1];
        const float4 Cv = p[2];
        X[0] = A.x;  Y[0] = A.y;  Z[0] = A.z;
        X[1] = A.w;  Y[1] = Bv.x; Z[1] = Bv.y;
        X[2] = Bv.z; Y[2] = Bv.w; Z[2] = Cv.x;
        X[3] = Cv.y; Y[3] = Cv.z; Z[3] = Cv.w;
        hv[0] = hv[1] = hv[2] = hv[3] = true;
    } else {
#pragma unroll
        for (int j = 0; j < 4; j++) {
            hv[j] = (gpart + i0 + j) < N;
            X[j] = Y[j] = Z[j] = 0.f;
            if (hv[j]) {
                X[j] = lpB[(i0 + j) * 3];
                Y[j] = lpB[(i0 + j) * 3 + 1];
                Z[j] = lpB[(i0 + j) * 3 + 2];
            }
        }
    }

    // ---- warp 0: quaternion -> camera matrix with folded translation -> smem ----
    if (tid < 32) {
        float qx = __ldg(rotq + b * 4 + 0);
        float qy = __ldg(rotq + b * 4 + 1);
        float qz = __ldg(rotq + b * 4 + 2);
        float qw = __ldg(rotq + b * 4 + 3);
        float inv = rsqrtf(qx * qx + qy * qy + qz * qz + qw * qw);
        qx = -qx * inv; qy = -qy * inv; qz = -qz * inv; qw = qw * inv;

        const float qx2 = qx * qx, qy2 = qy * qy, qz2 = qz * qz;
        const float qxqy = qx * qy, qxqz = qx * qz, qxqw = qx * qw;
        const float qyqz = qy * qz, qyqw = qy * qw, qzqw = qz * qw;
        const float r00 = 1.f - 2.f * qy2 - 2.f * qz2;
        const float r10 = 2.f * qxqy - 2.f * qzqw;
        const float r20 = 2.f * qxqz + 2.f * qyqw;
        const float r01 = 2.f * qxqy + 2.f * qzqw;
        const float r11 = 1.f - 2.f * qx2 - 2.f * qz2;
        const float r21 = 2.f * qyqz - 2.f * qxqw;
        const float r02 = 2.f * qxqz - 2.f * qyqw;
        const float r12 = 2.f * qyqz + 2.f * qxqw;
        const float r22 = 1.f - 2.f * qx2 - 2.f * qy2;

        const float cx = __ldg(pose + b * 3 + 0);
        const float cy = __ldg(pose + b * 3 + 1);
        const float cz = __ldg(pose + b * 3 + 2);
        const float t0 = cx * r00 + cy * r10 + cz * r20;
        const float t1 = cx * r01 + cy * r11 + cz * r21;
        const float t2 = cx * r02 + cy * r12 + cz * r22;

        if (tid == 0) {
            s_cam[0] = r00; s_cam[1]  = r10; s_cam[2]  = r20; s_cam[3]  = -t0;
            s_cam[4] = r01; s_cam[5]  = r11; s_cam[6]  = r21; s_cam[7]  = -t1;
            s_cam[8] = r02; s_cam[9]  = r12; s_cam[10] = r22; s_cam[11] = -t2;
        }
    }
    __syncthreads();   // publishes s_cam and s_cnt

    const float a00 = s_cam[0], a01 = s_cam[1],  a02 = s_cam[2],  a03 = s_cam[3];
    const float a10 = s_cam[4], a11 = s_cam[5],  a12 = s_cam[6],  a13 = s_cam[7];
    const float a20 = s_cam[8], a21 = s_cam[9],  a22 = s_cam[10], a23 = s_cam[11];

    const float* dimg = depth + b * HW;
    float*       oimg = out   + b * HW;

    // ---------------- Phase 1: project 4 particles (2 compaction rounds) ----------------
#pragma unroll
    for (int pair = 0; pair < 2; pair++) {
        float pxv[2], pyv[2], zv[2];
        bool  okv[2];
#pragma unroll
        for (int u = 0; u < 2; u++) {
            const int j = pair * 2 + u;
            const float z = fmaf(X[j], a20, fmaf(Y[j], a21, fmaf(Z[j], a22, a23)));
            bool ok = false;
            float px = 0.f, py = 0.f;
            if (hv[j] && z > 0.f) {
                const float x = fmaf(X[j], a00, fmaf(Y[j], a01, fmaf(Z[j], a02, a03)));
                const float y = fmaf(X[j], a10, fmaf(Y[j], a11, fmaf(Z[j], a12, a13)));
                const float invz = __frcp_rn(z);
                px = x * invz * CAM_FL + HALF_W;
                py = y * invz * CAM_FL + HALF_H;
                ok = (fabsf(px - HALF_W) <= 322.f) && (fabsf(py - HALF_H) <= 242.f);
            }
            okv[u] = ok; pxv[u] = px; pyv[u] = py; zv[u] = z;
        }

        const unsigned m0 = __ballot_sync(0xffffffffu, okv[0]);
        const unsigned m1 = __ballot_sync(0xffffffffu, okv[1]);
        const int n0  = __popc(m0);
        const int tot = n0 + __popc(m1);
        int idx[2] = {0, 0};
        if (tot) {
            const int lane = tid & 31;
            const unsigned lt = (1u << lane) - 1u;
            int base = 0;
            if (lane == 0) base = atomicAdd(&s_cnt, tot);
            base = __shfl_sync(0xffffffffu, base, 0);
            idx[0] = base + __popc(m0 & lt);
            idx[1] = base + n0 + __popc(m1 & lt);
        }

#pragma unroll
        for (int u = 0; u < 2; u++) {
            if (okv[u]) {
                const int id = idx[u];
                if (id < CAP) {
                    s_px[id] = pxv[u];
                    s_py[id] = pyv[u];
                    s_pz[id] = zv[u];
                } else {
                    // overflow slow path (statistically unreachable): direct splat
                    const float C1 = 0.60653066f, C2 = 0.13533528f;
                    const float px = pxv[u], py = pyv[u], z = zv[u];
                    const float fx = floorf(px), fy = floorf(py);
                    const int jb = (int)fx - 2, ib = (int)fy - 2;
                    const float uu = fx - px, vv = fy - py;
                    const float ax = __expf(-0.5f * uu * uu);
                    const float ex = __expf(-uu);
                    const float exi = __frcp_rn(ex);
                    const float wxv[5] = {ax*exi*exi*C2, ax*exi*C1, ax, ax*ex*C1, ax*ex*ex*C2};
                    const float ay = __expf(-0.5f * vv * vv);
                    const float ey = __expf(-vv);
                    const float eyi = __frcp_rn(ey);
                    const float wyv[5] = {ay*eyi*eyi*C2, ay*eyi*C1, ay, ay*ey*C1, ay*ey*ey*C2};
                    for (int ii = 0; ii < 5; ii++) {
                        const int yy = ib + ii;
                        if (yy < 0 || yy >= CAM_H) continue;
                        for (int jj = 0; jj < 5; jj++) {
                            const int xx = jb + jj;
                            if (xx < 0 || xx >= CAM_W) continue;
                            const float d = __ldg(dimg + yy * CAM_W + xx);
                            if (z <= d) atomicAdd(oimg + yy * CAM_W + xx, wyv[ii] * wxv[jj]);
                        }
                    }
                }
            }
        }
    }

    __syncthreads();

    // ---------------- Phase 1.5: dense weight/record computation ----------------
    const int cnt = min(s_cnt, CAP);
    {
        const float C1 = 0.60653066f;   // exp(-0.5)
        const float C2 = 0.13533528f;   // exp(-2)
        for (int t = tid; t < cnt; t += TPB) {
            const float px = s_px[t];
            const float py = s_py[t];
            const float z  = s_pz[t];

            const float fx = floorf(px), fy = floorf(py);
            const int jb = (int)fx - 2;
            const int ib = (int)fy - 2;                 // in [-4, 480]
            const int bx = min(max(jb, 0) & ~3, 632);   // aligned 8-slot window
            const int off = jb - bx;                    // in [-2, 8]
            const float u = fx - px;
            const float v = fy - py;

            const float ax  = __expf(-0.5f * u * u);
            const float ex  = __expf(-u);
            const float exi = __frcp_rn(ex);

            float* r = s_rec[t];
            *(float4*)(r)     = make_float4(0.f, 0.f, 0.f, 0.f);
            *(float4*)(r + 4) = make_float4(0.f, 0.f, 0.f, 0.f);
            int s;
            s = off + 0; if (s >= 0 && s <= 7) r[s] = ax * exi * exi * C2;
            s = off + 1; if (s >= 0 && s <= 7) r[s] = ax * exi * C1;
            s = off + 2; if (s >= 0 && s <= 7) r[s] = ax;
            s = off + 3; if (s >= 0 && s <= 7) r[s] = ax * ex * C1;
            s = off + 4; if (s >= 0 && s <= 7) r[s] = ax * ex * ex * C2;

            const float ay  = __expf(-0.5f * v * v);
            const float ey  = __expf(-v);
            const float eyi = __frcp_rn(ey);
            r[8]  = z;
            r[9]  = __int_as_float(bx | ((ib + 4) << 10));
            r[10] = ay * eyi * eyi * C2;
            r[11] = ay * eyi * C1;
            r[12] = ay;
            r[13] = ay * ey * C1;
            r[14] = ay * ey * ey * C2;
        }
    }

    __syncthreads();

    // ---------------- Phase 2: warp-coalesced splat ----------------
    // 8 consecutive lanes own the 8 aligned slots of one survivor; a warp
    // processes 4 survivors. Depth loads and reds hit 4 contiguous 32B
    // segments per warp-op (coalesced), 5 rows loaded up-front (MLP=5).
    const int wid  = tid >> 5;
    const int lane = tid & 31;
    const int sub  = lane >> 3;     // 0..3: survivor within warp-task
    const int slot = lane & 7;      // 0..7: x-slot

    for (int s0 = wid * 4; s0 < cnt; s0 += (TPB / 32) * 4) {
        const int s = s0 + sub;
        if (s >= cnt) continue;

        const float* r = s_rec[s];
        const float wx = r[slot];
        const float z  = r[8];
        const int   pk = __float_as_int(r[9]);
        const int   bx = pk & 0x3ff;
        const int   ib = ((pk >> 10) & 0x1ff) - 4;

        const int base = ib * CAM_W + bx + slot;

        float dd[5];
        int   oo[5];
        bool  rk[5];
#pragma unroll
        for (int row = 0; row < 5; row++) {
            const int yy = ib + row;
            rk[row] = (yy >= 0) && (yy < CAM_H) && (wx != 0.f);
            oo[row] = base + row * CAM_W;
            dd[row] = rk[row] ? __ldg(dimg + oo[row]) : -1.f;
        }
#pragma unroll
        for (int row = 0; row < 5; row++) {
            if (rk[row] && z <= dd[row]) {
                atomicAdd(oimg + oo[row], r[10 + row] * wx);
            }
        }
    }
}

extern "C" void kernel_launch(void* const* d_in, const int* in_sizes, int n_in,
                              void* d_out, int out_size) {
    const float* locs  = (const float*)d_in[0];
    const float* pose  = (const float*)d_in[1];
    const float* rotq  = (const float*)d_in[2];
    const float* depth = (const float*)d_in[3];
    float* out = (float*)d_out;

    const int B = in_sizes[1] / 3;           // 4
    const int N = in_sizes[0] / (3 * B);     // 200000

    cudaMemsetAsync(d_out, 0, (size_t)out_size * sizeof(float), 0);

    dim3 grid((N + PB - 1) / PB, B);
    proj_kernel<<<grid, TPB>>>(locs, pose, rotq, depth, out, N);
}